// round 4
// baseline (speedup 1.0000x reference)
#include <cuda_runtime.h>

#define NBLK 128
#define NTHR 256

// persistent state (allocation-free scratch)
__device__ float g_h0[512 * 512];
__device__ float g_h1[512 * 512];
__device__ float g_c[512 * 512];
__device__ int   g_idx[512];
__device__ unsigned g_count;
__device__ unsigned g_gen;

__device__ __forceinline__ void grid_sync() {
    __syncthreads();
    if (threadIdx.x == 0) {
        __threadfence();
        unsigned gen = *((volatile unsigned*)&g_gen);
        if (atomicAdd(&g_count, 1u) == NBLK - 1u) {
            g_count = 0u;
            __threadfence();
            *((volatile unsigned*)&g_gen) = gen + 1u;
        } else {
            while (*((volatile unsigned*)&g_gen) == gen) { }
        }
    }
    __syncthreads();
}

// packed fp32x2 helpers (SASS FFMA2 path, PTX-only)
__device__ __forceinline__ unsigned long long dup2(float a) {
    unsigned long long r;
    unsigned u = __float_as_uint(a);
    asm("mov.b64 %0, {%1, %1};" : "=l"(r) : "r"(u));
    return r;
}
__device__ __forceinline__ void fma2(unsigned long long& d, unsigned long long a,
                                     unsigned long long b) {
    asm("fma.rn.f32x2 %0, %1, %2, %0;" : "+l"(d) : "l"(a), "l"(b));
}
__device__ __forceinline__ float2 unpack2(unsigned long long v) {
    unsigned lo, hi;
    asm("mov.b64 {%0, %1}, %2;" : "=r"(lo), "=r"(hi) : "l"(v));
    return make_float2(__uint_as_float(lo), __uint_as_float(hi));
}

// Bs column swizzle: 16B-granularity XOR keeps every 8-lane phase conflict-free
__device__ __forceinline__ int swz(int c) { return c ^ (((c >> 5) & 1) << 2); }

__global__ void __launch_bounds__(NTHR)
decoder_kernel(const float* __restrict__ x,
               const float* __restrict__ W_ih,
               const float* __restrict__ W_hh,
               const float* __restrict__ b_ih,
               const float* __restrict__ b_hh,
               float* __restrict__ out) {
    extern __shared__ float smem[];
    float* As = smem;            // [64 rows][64 k] row-major
    float* Bs = smem + 64 * 64;  // [64 k][128 cols] k-major, swizzled columns

    const int tid = threadIdx.x, bid = blockIdx.x;
    const int tb = bid >> 4, tv = bid & 15;
    const int rb0 = tb << 6;   // batch-row tile base (64 rows)
    const int vt0 = tv << 5;   // v tile base (32 v)
    const int ty = tid >> 4, tx = tid & 15;

    // per-thread column mapping: local col c = tx*8 + j ; gate = c&3, v = vt0 + (c>>2)
    float bsum[8];
#pragma unroll
    for (int j = 0; j < 8; ++j) {
        int c = (tx << 3) + j;
        int colg = ((c & 3) << 9) + vt0 + (c >> 2);
        bsum[j] = b_ih[colg] + b_hh[colg];
    }

    // swizzled load offsets for the compute loop
    const int xr  = ((tx >> 2) & 1) << 2;
    const int b0p = (tx << 3) | xr;        // physical addr of logical cols [tx*8, tx*8+4)
    const int b1p = (tx << 3) | (4 ^ xr);  // physical addr of logical cols [tx*8+4, tx*8+8)

    // Bs staging: thread's W_hh row (gate-interleaved local columns)
    const int sc = tid & 127;
    const int scp = swz(sc);          // swizzled physical column for stores
    const int skh = (tid >> 7) << 5;  // 0 or 32 (k half)
    const float* wrow = W_hh + ((size_t)(((sc & 3) << 9) + vt0 + (sc >> 2)) << 9);

    // As staging mapping
    const int sr = tid >> 4;          // 0..15
    const int skq = (tid & 15) << 2;  // 0..60

    // ---- init: h0 = x, c = 0, idx = SOS(=1), out[:,127,:] = one_hot(PAD=0)
    for (int i = bid * NTHR + tid; i < 512 * 512; i += NBLK * NTHR) {
        g_h0[i] = x[i];
        g_c[i] = 0.f;
        int b = i >> 9, v = i & 511;
        out[((size_t)b << 16) + (127 << 9) + v] = (v == 0) ? 1.f : 0.f;
    }
    for (int i = bid * NTHR + tid; i < 512; i += NBLK * NTHR) g_idx[i] = 1;
    grid_sync();

    for (int t = 0; t < 127; ++t) {
        const float* __restrict__ hin = (t & 1) ? g_h1 : g_h0;
        float* __restrict__ hout      = (t & 1) ? g_h0 : g_h1;

        // ============ phase A: gates = hin @ W_hh_sel^T (fp32x2 packed FFMA) ======
        unsigned long long acc[4][4];
#pragma unroll
        for (int i = 0; i < 4; ++i)
#pragma unroll
            for (int p = 0; p < 4; ++p) acc[i][p] = 0ull;

        for (int kc0 = 0; kc0 < 512; kc0 += 64) {
            __syncthreads();
            // stage As (coalesced float4, conflict-free)
#pragma unroll
            for (int rr = 0; rr < 4; ++rr) {
                int row = (rr << 4) + sr;
                float4 v4 = *(const float4*)&hin[((size_t)(rb0 + row) << 9) + kc0 + skq];
                *(float4*)&As[(row << 6) + skq] = v4;
            }
            // stage Bs k-major, swizzled (per-warp bank permutation: conflict-free)
#pragma unroll
            for (int j = 0; j < 8; ++j) {
                int k0 = skh + (j << 2);
                float4 v4 = *(const float4*)&wrow[kc0 + k0];
                Bs[((k0 + 0) << 7) + scp] = v4.x;
                Bs[((k0 + 1) << 7) + scp] = v4.y;
                Bs[((k0 + 2) << 7) + scp] = v4.z;
                Bs[((k0 + 3) << 7) + scp] = v4.w;
            }
            __syncthreads();

#pragma unroll 2
            for (int kq = 0; kq < 16; ++kq) {
                float4 a4[4];
#pragma unroll
                for (int i = 0; i < 4; ++i)
                    a4[i] = *(const float4*)&As[((((ty << 2) + i)) << 6) + (kq << 2)];
#pragma unroll
                for (int kk = 0; kk < 4; ++kk) {
                    const int kr = (kq << 2) + kk;
                    ulonglong2 b0 = *(const ulonglong2*)&Bs[(kr << 7) + b0p];
                    ulonglong2 b1 = *(const ulonglong2*)&Bs[(kr << 7) + b1p];
#pragma unroll
                    for (int i = 0; i < 4; ++i) {
                        float a = ((const float*)&a4[i])[kk];
                        unsigned long long ap = dup2(a);
                        fma2(acc[i][0], ap, b0.x);
                        fma2(acc[i][1], ap, b0.y);
                        fma2(acc[i][2], ap, b1.x);
                        fma2(acc[i][3], ap, b1.y);
                    }
                }
            }
        }

        // ---- epilogue: + bias + W_ih[:, idx_b] gather, LSTM cell update
        {
            const int v0 = vt0 + (tx << 1);
#pragma unroll
            for (int i = 0; i < 4; ++i) {
                const int b = rb0 + (ty << 2) + i;
                const int idx = g_idx[b];
#pragma unroll
                for (int vv = 0; vv < 2; ++vv) {
                    const int v = v0 + vv;
                    float2 pa = unpack2(acc[i][(vv << 1) + 0]);  // gates i, f
                    float2 pb = unpack2(acc[i][(vv << 1) + 1]);  // gates g, o
                    const size_t o = ((size_t)v << 9) + (size_t)idx;
                    float gi = pa.x + bsum[(vv << 2) + 0] + W_ih[o];
                    float gf = pa.y + bsum[(vv << 2) + 1] + W_ih[262144 + o];
                    float gg = pb.x + bsum[(vv << 2) + 2] + W_ih[524288 + o];
                    float go = pb.y + bsum[(vv << 2) + 3] + W_ih[786432 + o];
                    float si = 1.f / (1.f + expf(-gi));
                    float sf = 1.f / (1.f + expf(-gf));
                    float so = 1.f / (1.f + expf(-go));
                    float tg = tanhf(gg);
                    const size_t hcix = ((size_t)b << 9) + v;
                    float cn = sf * g_c[hcix] + si * tg;
                    g_c[hcix] = cn;
                    hout[hcix] = so * tanhf(cn);
                }
            }
        }

        grid_sync();

        // ============ phase B: softmax + argmax, one warp per batch row ==========
        {
            int w = (bid << 3) + (tid >> 5);
            if (w < 512) {
                int lane = tid & 31;
                const float* hr = hout + ((size_t)w << 9);
                float4 hv[4];
#pragma unroll
                for (int q = 0; q < 4; ++q)
                    hv[q] = *(const float4*)&hr[(q << 7) + (lane << 2)];

                float bm = -1e30f; int bi = 0x7fffffff;
#pragma unroll
                for (int q = 0; q < 4; ++q) {
                    const float* f = (const float*)&hv[q];
#pragma unroll
                    for (int cc = 0; cc < 4; ++cc) {
                        int vi = (q << 7) + (lane << 2) + cc;
                        float val = f[cc];
                        if (val > bm || (val == bm && vi < bi)) { bm = val; bi = vi; }
                    }
                }
#pragma unroll
                for (int off = 16; off; off >>= 1) {
                    float om = __shfl_down_sync(0xffffffffu, bm, off);
                    int   oi = __shfl_down_sync(0xffffffffu, bi, off);
                    if (om > bm || (om == bm && oi < bi)) { bm = om; bi = oi; }
                }
                bm = __shfl_sync(0xffffffffu, bm, 0);
                bi = __shfl_sync(0xffffffffu, bi, 0);

                float e[16];
                float s = 0.f;
#pragma unroll
                for (int q = 0; q < 4; ++q) {
                    const float* f = (const float*)&hv[q];
#pragma unroll
                    for (int cc = 0; cc < 4; ++cc) {
                        float ev = expf(f[cc] - bm);
                        e[(q << 2) + cc] = ev;
                        s += ev;
                    }
                }
#pragma unroll
                for (int off = 16; off; off >>= 1)
                    s += __shfl_xor_sync(0xffffffffu, s, off);
                float inv = 1.f / s;

                float* orow = out + ((size_t)w << 16) + ((size_t)t << 9);
#pragma unroll
                for (int q = 0; q < 4; ++q) {
                    float4 ov;
                    ov.x = e[(q << 2) + 0] * inv;
                    ov.y = e[(q << 2) + 1] * inv;
                    ov.z = e[(q << 2) + 2] * inv;
                    ov.w = e[(q << 2) + 3] * inv;
                    *(float4*)&orow[(q << 7) + (lane << 2)] = ov;
                }
                if (lane == 0) g_idx[w] = bi;
            }
        }
        grid_sync();
    }
}

extern "C" void kernel_launch(void* const* d_in, const int* in_sizes, int n_in,
                              void* d_out, int out_size) {
    const float* x    = (const float*)d_in[0];
    const float* W_ih = (const float*)d_in[1];
    const float* W_hh = (const float*)d_in[2];
    const float* b_ih = (const float*)d_in[3];
    const float* b_hh = (const float*)d_in[4];
    float* out = (float*)d_out;
    decoder_kernel<<<NBLK, NTHR, 48 * 1024>>>(x, W_ih, W_hh, b_ih, b_hh, out);
}

// round 12
// speedup vs baseline: 1.0762x; 1.0762x over previous
#include <cuda_runtime.h>
#include <cuda_bf16.h>
#include <cstdint>

#define NBLK 128
#define NTHR 256

// ---------------- persistent device state (allocation-free) ----------------
__device__ __nv_bfloat16 g_ha[2][3][512 * 512];   // h splits, ping-pong
__device__ __nv_bfloat16 g_w[3][2048 * 512];      // W_hh splits (static)
__device__ float g_WihT[512 * 2048];              // W_ih transposed [idx][gatecol]
__device__ float g_h[512 * 512];
__device__ float g_c[512 * 512];
__device__ int   g_idx[512];
__device__ unsigned g_count;
__device__ unsigned g_gen;

__device__ __forceinline__ void grid_sync() {
    __syncthreads();
    if (threadIdx.x == 0) {
        __threadfence();
        unsigned gen = *((volatile unsigned*)&g_gen);
        if (atomicAdd(&g_count, 1u) == NBLK - 1u) {
            g_count = 0u;
            __threadfence();
            *((volatile unsigned*)&g_gen) = gen + 1u;
        } else {
            while (*((volatile unsigned*)&g_gen) == gen) { }
        }
    }
    __syncthreads();
}

__device__ __forceinline__ uint32_t smem_u32(const void* p) {
    uint32_t a;
    asm("{ .reg .u64 t; cvta.to.shared.u64 t, %1; cvt.u32.u64 %0, t; }" : "=r"(a) : "l"(p));
    return a;
}

// ---------------- baseline-PTX tensor path (sm_80+: works on plain sm_103) --
__device__ __forceinline__ void ldsm4(uint32_t* r, uint32_t addr) {
    asm volatile("ldmatrix.sync.aligned.m8n8.x4.shared.b16 {%0,%1,%2,%3}, [%4];"
                 : "=r"(r[0]), "=r"(r[1]), "=r"(r[2]), "=r"(r[3]) : "r"(addr));
}
__device__ __forceinline__ void mma16816(float* d, const uint32_t* a, const uint32_t* b) {
    asm volatile("mma.sync.aligned.m16n8k16.row.col.f32.bf16.bf16.f32 "
                 "{%0,%1,%2,%3}, {%4,%5,%6,%7}, {%8,%9}, {%0,%1,%2,%3};"
                 : "+f"(d[0]), "+f"(d[1]), "+f"(d[2]), "+f"(d[3])
                 : "r"(a[0]), "r"(a[1]), "r"(a[2]), "r"(a[3]), "r"(b[0]), "r"(b[1]));
}
#define CP16(dst, src) \
    asm volatile("cp.async.cg.shared.global [%0], [%1], 16;" :: "r"(dst), "l"(src))
#define CP_COMMIT() asm volatile("cp.async.commit_group;" ::: "memory")
#define CP_WAIT0()  asm volatile("cp.async.wait_group 0;" ::: "memory")

// smem layout (bytes). A/B tiles: 144B row stride (128B data + 16B pad ->
// ldmatrix reads 8 rows at 144B stride: banks spread, conflict-free).
#define OFF_BIAS 256
#define OFF_A    1024                       // 3 x (128 rows x 144B) = 55296
#define OFF_B    (1024 + 3 * 18432)         // 3 x (64 rows x 144B)  = 27648
#define SMEM_SZ  (OFF_B + 3 * 9216)         // 83968
#define GSTRIDE  65                          // gates overlay: f32[128][65] at OFF_A

__device__ __forceinline__ void split3(float v, __nv_bfloat16& s1,
                                       __nv_bfloat16& s2, __nv_bfloat16& s3) {
    s1 = __float2bfloat16(v);
    float r = v - __bfloat162float(s1);
    s2 = __float2bfloat16(r);
    float r2 = r - __bfloat162float(s2);
    s3 = __float2bfloat16(r2);
}

__global__ void __launch_bounds__(NTHR, 1)
decoder_kernel(const float* __restrict__ x,
               const float* __restrict__ W_ih,
               const float* __restrict__ W_hh,
               const float* __restrict__ b_ih,
               const float* __restrict__ b_hh,
               float* __restrict__ out) {
    extern __shared__ __align__(1024) char smem[];
    float* sbias = (float*)(smem + OFF_BIAS);
    float* gsh = (float*)(smem + OFF_A);   // gates overlay (after last chunk)

    const int tid = threadIdx.x, bid = blockIdx.x;
    const int wid = tid >> 5, lane = tid & 31;
    const int bt = bid >> 5;          // batch tile (0..3): 128 rows
    const int ct = bid & 31;          // col tile (0..31): 16 v
    const int rowbase = bt << 7;
    const int vt0 = ct << 4;
    const int mw = wid >> 1, nw = wid & 1;  // warp tile: rows mw*32, cols nw*32

    const uint32_t sbase = smem_u32(smem);

    // ---------------- init ----------------
    for (int i = bid * NTHR + tid; i < 512 * 512; i += NBLK * NTHR) {
        float xv = x[i];
        split3(xv, g_ha[0][0][i], g_ha[0][1][i], g_ha[0][2][i]);
        g_c[i] = 0.f;
        int b = i >> 9, v = i & 511;
        out[((size_t)b << 16) + (127 << 9) + v] = (v == 0) ? 1.f : 0.f;
    }
    for (int i = bid * NTHR + tid; i < 2048 * 512; i += NBLK * NTHR) {
        float wv = W_hh[i];
        split3(wv, g_w[0][i], g_w[1][i], g_w[2][i]);
    }
    for (int i = bid * NTHR + tid; i < 512 * 2048; i += NBLK * NTHR) {
        int idx = i >> 11, gc = i & 2047;
        g_WihT[i] = W_ih[gc * 512 + idx];
    }
    for (int i = bid * NTHR + tid; i < 512; i += NBLK * NTHR) g_idx[i] = 1;

    if (tid < 64) {
        int colg = ((tid & 3) << 9) + vt0 + (tid >> 2);
        sbias[tid] = b_ih[colg] + b_hh[colg];
    }
    grid_sync();

    // ldmatrix per-lane address components
    const int a_row = lane & 15;                 // A: row within m16 tile
    const int a_kb  = (lane >> 4) << 4;          // A: 16B k-offset (k8 group)
    const int b_n   = ((lane >> 4) << 3) + (lane & 7);  // B: n within n16 pair
    const int b_kb  = ((lane >> 3) & 1) << 4;    // B: 16B k-offset

    for (int t = 0; t < 127; ++t) {
        const int cur = t & 1, nxt = cur ^ 1;

        float acc[2][4][4];
#pragma unroll
        for (int i = 0; i < 2; ++i)
#pragma unroll
            for (int j = 0; j < 4; ++j)
#pragma unroll
                for (int q = 0; q < 4; ++q) acc[i][j][q] = 0.f;

        // ============ 8 k-chunks of 64: cp.async stage + mma.sync ============
        for (int ci = 0; ci < 8; ++ci) {
            const int kc0 = ci << 6;
            // stage 3 A tiles (128x64) + 3 B tiles (64x64), 16B vectors
#pragma unroll
            for (int it = 0; it < 18; ++it) {
                int u = it * 256 + tid;
                if (u < 3072) {
                    int s = u >> 10, r = u & 1023, row = r >> 3, kv = r & 7;
                    const __nv_bfloat16* src =
                        &g_ha[cur][s][(((size_t)(rowbase + row)) << 9) + kc0 + (kv << 3)];
                    uint32_t dst = sbase + OFF_A + s * 18432 + row * 144 + (kv << 4);
                    CP16(dst, src);
                } else {
                    int u2 = u - 3072;
                    int s = u2 >> 9, r = u2 & 511, row = r >> 3, kv = r & 7;
                    int wrow = ((row & 3) << 9) + vt0 + (row >> 2);
                    const __nv_bfloat16* src =
                        &g_w[s][(((size_t)wrow) << 9) + kc0 + (kv << 3)];
                    uint32_t dst = sbase + OFF_B + s * 9216 + row * 144 + (kv << 4);
                    CP16(dst, src);
                }
            }
            CP_COMMIT();
            CP_WAIT0();
            __syncthreads();

            // compute: 4 k16 steps
#pragma unroll
            for (int kk = 0; kk < 4; ++kk) {
                const int kb = kk << 5;  // 16 bf16 = 32 bytes
                uint32_t af[3][2][4], bf[3][2][4];
#pragma unroll
                for (int s = 0; s < 3; ++s) {
#pragma unroll
                    for (int i = 0; i < 2; ++i) {
                        int row = (mw << 5) + (i << 4) + a_row;
                        ldsm4(af[s][i],
                              sbase + OFF_A + s * 18432 + row * 144 + kb + a_kb);
                    }
#pragma unroll
                    for (int jj = 0; jj < 2; ++jj) {
                        int n = (nw << 5) + (jj << 4) + b_n;
                        ldsm4(bf[s][jj],
                              sbase + OFF_B + s * 9216 + n * 144 + kb + b_kb);
                    }
                }
                // 6 split-pairs: (0,0),(0,1),(1,0),(1,1),(0,2),(2,0)
                const int sa[6] = {0, 0, 1, 1, 0, 2};
                const int sb[6] = {0, 1, 0, 1, 2, 0};
#pragma unroll
                for (int p = 0; p < 6; ++p) {
#pragma unroll
                    for (int i = 0; i < 2; ++i)
#pragma unroll
                        for (int j = 0; j < 4; ++j)
                            mma16816(acc[i][j], af[sa[p]][i],
                                     &bf[sb[p]][j >> 1][(j & 1) << 1]);
                }
            }
            __syncthreads();  // before next chunk's stage overwrites tiles
        }

        // ---- write gates to smem (overlay on A region) ----
#pragma unroll
        for (int i = 0; i < 2; ++i)
#pragma unroll
            for (int j = 0; j < 4; ++j) {
                int row = (mw << 5) + (i << 4) + (lane >> 2);
                int col = (nw << 5) + (j << 3) + ((lane & 3) << 1);
                gsh[row * GSTRIDE + col]           = acc[i][j][0];
                gsh[row * GSTRIDE + col + 1]       = acc[i][j][1];
                gsh[(row + 8) * GSTRIDE + col]     = acc[i][j][2];
                gsh[(row + 8) * GSTRIDE + col + 1] = acc[i][j][3];
            }
        __syncthreads();

        // ============ epilogue: bias + W_ih gather + LSTM + split ============
        if (tid < 128) {
            const int b = rowbase + tid;
            const int idx = g_idx[b];
            const float* wt = g_WihT + (size_t)idx * 2048;
            const float* gr = gsh + tid * GSTRIDE;
#pragma unroll
            for (int vl = 0; vl < 16; ++vl) {
                const int v = vt0 + vl;
                const int c0 = vl << 2;
                float gi = gr[c0 + 0] + sbias[c0 + 0] + wt[v];
                float gf = gr[c0 + 1] + sbias[c0 + 1] + wt[512 + v];
                float gg = gr[c0 + 2] + sbias[c0 + 2] + wt[1024 + v];
                float go = gr[c0 + 3] + sbias[c0 + 3] + wt[1536 + v];
                float si = 1.f / (1.f + expf(-gi));
                float sf = 1.f / (1.f + expf(-gf));
                float so = 1.f / (1.f + expf(-go));
                float tg = tanhf(gg);
                const size_t cix = ((size_t)b << 9) + v;
                float cn = sf * g_c[cix] + si * tg;
                g_c[cix] = cn;
                float h = so * tanhf(cn);
                g_h[cix] = h;
                split3(h, g_ha[nxt][0][cix], g_ha[nxt][1][cix], g_ha[nxt][2][cix]);
            }
        }
        grid_sync();

        // ============ phase B: softmax + argmax, one warp per batch row ======
        if (wid < 4) {
            int w = (bid << 2) + wid;
            const float* hr = g_h + ((size_t)w << 9);
            float4 hv[4];
#pragma unroll
            for (int q = 0; q < 4; ++q)
                hv[q] = *(const float4*)&hr[(q << 7) + (lane << 2)];

            float bm = -1e30f; int bi = 0x7fffffff;
#pragma unroll
            for (int q = 0; q < 4; ++q) {
                const float* f = (const float*)&hv[q];
#pragma unroll
                for (int cc = 0; cc < 4; ++cc) {
                    int vi = (q << 7) + (lane << 2) + cc;
                    float val = f[cc];
                    if (val > bm || (val == bm && vi < bi)) { bm = val; bi = vi; }
                }
            }
#pragma unroll
            for (int off = 16; off; off >>= 1) {
                float om = __shfl_down_sync(0xffffffffu, bm, off);
                int   oi = __shfl_down_sync(0xffffffffu, bi, off);
                if (om > bm || (om == bm && oi < bi)) { bm = om; bi = oi; }
            }
            bm = __shfl_sync(0xffffffffu, bm, 0);
            bi = __shfl_sync(0xffffffffu, bi, 0);

            float e[16];
            float s = 0.f;
#pragma unroll
            for (int q = 0; q < 4; ++q) {
                const float* f = (const float*)&hv[q];
#pragma unroll
                for (int cc = 0; cc < 4; ++cc) {
                    float ev = expf(f[cc] - bm);
                    e[(q << 2) + cc] = ev;
                    s += ev;
                }
            }
#pragma unroll
            for (int off = 16; off; off >>= 1)
                s += __shfl_xor_sync(0xffffffffu, s, off);
            float inv = 1.f / s;

            float* orow = out + ((size_t)w << 16) + ((size_t)t << 9);
#pragma unroll
            for (int q = 0; q < 4; ++q) {
                float4 ov;
                ov.x = e[(q << 2) + 0] * inv;
                ov.y = e[(q << 2) + 1] * inv;
                ov.z = e[(q << 2) + 2] * inv;
                ov.w = e[(q << 2) + 3] * inv;
                *(float4*)&orow[(q << 7) + (lane << 2)] = ov;
            }
            if (lane == 0) g_idx[w] = bi;
        }
        grid_sync();
    }
}

extern "C" void kernel_launch(void* const* d_in, const int* in_sizes, int n_in,
                              void* d_out, int out_size) {
    const float* x    = (const float*)d_in[0];
    const float* W_ih = (const float*)d_in[1];
    const float* W_hh = (const float*)d_in[2];
    const float* b_ih = (const float*)d_in[3];
    const float* b_hh = (const float*)d_in[4];
    float* out = (float*)d_out;
    cudaFuncSetAttribute(decoder_kernel,
                         cudaFuncAttributeMaxDynamicSharedMemorySize, SMEM_SZ);
    decoder_kernel<<<NBLK, NTHR, SMEM_SZ>>>(x, W_ih, W_hh, b_ih, b_hh, out);
}

// round 16
// speedup vs baseline: 1.1333x; 1.0530x over previous
#include <cuda_runtime.h>
#include <cuda_bf16.h>
#include <cstdint>

#define NBLK 128
#define NTHR 256

// ---------------- persistent device state (allocation-free) ----------------
__device__ __nv_bfloat16 g_ha[2][3][512 * 512];   // h splits, ping-pong
__device__ __nv_bfloat16 g_w[3][2048 * 512];      // W_hh splits (static)
__device__ float g_WihT[512 * 2048];              // W_ih transposed [idx][gatecol]
__device__ float g_h[512 * 512];
__device__ float g_c[512 * 512];
__device__ int   g_idx[512];
__device__ unsigned g_count;
__device__ unsigned g_gen;

__device__ __forceinline__ void grid_sync() {
    __syncthreads();
    if (threadIdx.x == 0) {
        __threadfence();
        unsigned gen = *((volatile unsigned*)&g_gen);
        if (atomicAdd(&g_count, 1u) == NBLK - 1u) {
            g_count = 0u;
            __threadfence();
            *((volatile unsigned*)&g_gen) = gen + 1u;
        } else {
            while (*((volatile unsigned*)&g_gen) == gen) { }
        }
    }
    __syncthreads();
}

__device__ __forceinline__ uint32_t smem_u32(const void* p) {
    uint32_t a;
    asm("{ .reg .u64 t; cvta.to.shared.u64 t, %1; cvt.u32.u64 %0, t; }" : "=r"(a) : "l"(p));
    return a;
}

// ---------------- baseline-PTX tensor path (sm_80+) ----------------
__device__ __forceinline__ void ldsm4(uint32_t* r, uint32_t addr) {
    asm volatile("ldmatrix.sync.aligned.m8n8.x4.shared.b16 {%0,%1,%2,%3}, [%4];"
                 : "=r"(r[0]), "=r"(r[1]), "=r"(r[2]), "=r"(r[3]) : "r"(addr));
}
__device__ __forceinline__ void mma16816(float* d, const uint32_t* a, const uint32_t* b) {
    asm volatile("mma.sync.aligned.m16n8k16.row.col.f32.bf16.bf16.f32 "
                 "{%0,%1,%2,%3}, {%4,%5,%6,%7}, {%8,%9}, {%0,%1,%2,%3};"
                 : "+f"(d[0]), "+f"(d[1]), "+f"(d[2]), "+f"(d[3])
                 : "r"(a[0]), "r"(a[1]), "r"(a[2]), "r"(a[3]), "r"(b[0]), "r"(b[1]));
}
#define CP16(dst, src) \
    asm volatile("cp.async.cg.shared.global [%0], [%1], 16;" :: "r"(dst), "l"(src))
#define CP_COMMIT() asm volatile("cp.async.commit_group;" ::: "memory")
#define CP_WAIT0()  asm volatile("cp.async.wait_group 0;" ::: "memory")
#define CP_WAIT1()  asm volatile("cp.async.wait_group 1;" ::: "memory")

// smem layout (bytes). 144B row stride (128B data + 16B pad: conflict-free ldmatrix).
// Double-buffered chunk staging.
#define ABUF 55296                    // 3 x (128 rows x 144B)
#define BBUF 27648                    // 3 x (64 rows x 144B)
#define SBUF (ABUF + BBUF)            // 82944
#define OFF_BIAS 256
#define OFF_BUF 1024
#define SMEM_SZ (OFF_BUF + 2 * SBUF)  // 166912
#define GSTRIDE 65                    // gates overlay f32[128][65] on buffer-0 A

__device__ __forceinline__ void split3(float v, __nv_bfloat16& s1,
                                       __nv_bfloat16& s2, __nv_bfloat16& s3) {
    s1 = __float2bfloat16(v);
    float r = v - __bfloat162float(s1);
    s2 = __float2bfloat16(r);
    float r2 = r - __bfloat162float(s2);
    s3 = __float2bfloat16(r2);
}

// stage one k-chunk (3 A tiles 128x64 + 3 B tiles 64x64, bf16) into buffer `buf`
__device__ __forceinline__ void stage_chunk(uint32_t sbase, int buf,
                                            const __nv_bfloat16* hab,
                                            int rowbase, int vt0, int kc0, int tid) {
    const uint32_t aB = sbase + OFF_BUF + buf * SBUF;
    const uint32_t bB = aB + ABUF;
#pragma unroll
    for (int it = 0; it < 18; ++it) {
        int u = it * 256 + tid;
        if (u < 3072) {
            int s = u >> 10, r = u & 1023, row = r >> 3, kv = r & 7;
            const __nv_bfloat16* src =
                hab + s * 262144 + ((rowbase + row) << 9) + kc0 + (kv << 3);
            CP16(aB + s * 18432 + row * 144 + (kv << 4), src);
        } else {
            int u2 = u - 3072;
            int s = u2 >> 9, r = u2 & 511, row = r >> 3, kv = r & 7;
            int wrow = ((row & 3) << 9) + vt0 + (row >> 2);
            const __nv_bfloat16* src =
                &g_w[0][0] + s * 1048576 + (((size_t)wrow) << 9) + kc0 + (kv << 3);
            CP16(bB + s * 9216 + row * 144 + (kv << 4), src);
        }
    }
}

__global__ void __launch_bounds__(NTHR, 1)
decoder_kernel(const float* __restrict__ x,
               const float* __restrict__ W_ih,
               const float* __restrict__ W_hh,
               const float* __restrict__ b_ih,
               const float* __restrict__ b_hh,
               float* __restrict__ out) {
    extern __shared__ __align__(1024) char smem[];
    float* sbias = (float*)(smem + OFF_BIAS);
    float* gsh = (float*)(smem + OFF_BUF);   // gates overlay (buffer-0 A region)

    const int tid = threadIdx.x, bid = blockIdx.x;
    const int wid = tid >> 5, lane = tid & 31;
    const int bt = bid >> 5;          // batch tile (0..3): 128 rows
    const int ct = bid & 31;          // col tile (0..31): 16 v
    const int rowbase = bt << 7;
    const int vt0 = ct << 4;
    const int mw = wid >> 1, nw = wid & 1;  // warp tile: rows mw*32, cols nw*32

    const uint32_t sbase = smem_u32(smem);

    // ---------------- init ----------------
    for (int i = bid * NTHR + tid; i < 512 * 512; i += NBLK * NTHR) {
        float xv = x[i];
        split3(xv, g_ha[0][0][i], g_ha[0][1][i], g_ha[0][2][i]);
        g_c[i] = 0.f;
        int b = i >> 9, v = i & 511;
        out[((size_t)b << 16) + (127 << 9) + v] = (v == 0) ? 1.f : 0.f;
    }
    for (int i = bid * NTHR + tid; i < 2048 * 512; i += NBLK * NTHR) {
        float wv = W_hh[i];
        split3(wv, g_w[0][i], g_w[1][i], g_w[2][i]);
    }
    for (int i = bid * NTHR + tid; i < 512 * 2048; i += NBLK * NTHR) {
        int idx = i >> 11, gc = i & 2047;
        g_WihT[i] = W_ih[gc * 512 + idx];
    }
    for (int i = bid * NTHR + tid; i < 512; i += NBLK * NTHR) g_idx[i] = 1;

    if (tid < 64) {
        int colg = ((tid & 3) << 9) + vt0 + (tid >> 2);
        sbias[tid] = b_ih[colg] + b_hh[colg];
    }
    grid_sync();

    // ldmatrix per-lane address components
    const int a_row = lane & 15;
    const int a_kb  = (lane >> 4) << 4;
    const int b_n   = ((lane >> 4) << 3) + (lane & 7);
    const int b_kb  = ((lane >> 3) & 1) << 4;

    for (int t = 0; t < 127; ++t) {
        const int cur = t & 1, nxt = cur ^ 1;
        const __nv_bfloat16* hab = &g_ha[cur][0][0];

        float acc[2][4][4];
#pragma unroll
        for (int i = 0; i < 2; ++i)
#pragma unroll
            for (int j = 0; j < 4; ++j)
#pragma unroll
                for (int q = 0; q < 4; ++q) acc[i][j][q] = 0.f;

        // ======== 8 k-chunks of 64, double-buffered cp.async staging ========
        stage_chunk(sbase, 0, hab, rowbase, vt0, 0, tid);
        CP_COMMIT();
        for (int ci = 0; ci < 8; ++ci) {
            if (ci < 7) {
                stage_chunk(sbase, (ci + 1) & 1, hab, rowbase, vt0, (ci + 1) << 6, tid);
                CP_COMMIT();
                CP_WAIT1();   // chunk ci landed; chunk ci+1 still in flight
            } else {
                CP_WAIT0();
            }
            __syncthreads();

            const uint32_t aB = sbase + OFF_BUF + (ci & 1) * SBUF;
            const uint32_t bB = aB + ABUF;
#pragma unroll
            for (int kk = 0; kk < 4; ++kk) {
                const int kb = kk << 5;
                uint32_t af[3][2][4], bf[3][2][4];
#pragma unroll
                for (int s = 0; s < 3; ++s) {
#pragma unroll
                    for (int i = 0; i < 2; ++i) {
                        int row = (mw << 5) + (i << 4) + a_row;
                        ldsm4(af[s][i], aB + s * 18432 + row * 144 + kb + a_kb);
                    }
#pragma unroll
                    for (int jj = 0; jj < 2; ++jj) {
                        int n = (nw << 5) + (jj << 4) + b_n;
                        ldsm4(bf[s][jj], bB + s * 9216 + n * 144 + kb + b_kb);
                    }
                }
                const int sa[6] = {0, 0, 1, 1, 0, 2};
                const int sb[6] = {0, 1, 0, 1, 2, 0};
#pragma unroll
                for (int p = 0; p < 6; ++p) {
#pragma unroll
                    for (int i = 0; i < 2; ++i)
#pragma unroll
                        for (int j = 0; j < 4; ++j)
                            mma16816(acc[i][j], af[sa[p]][i],
                                     &bf[sb[p]][j >> 1][(j & 1) << 1]);
                }
            }
            __syncthreads();  // buffer reuse fence (staged 2 chunks ahead)
        }

        // ---- write gates to smem (overlay on buffer-0 A region) ----
#pragma unroll
        for (int i = 0; i < 2; ++i)
#pragma unroll
            for (int j = 0; j < 4; ++j) {
                int row = (mw << 5) + (i << 4) + (lane >> 2);
                int col = (nw << 5) + (j << 3) + ((lane & 3) << 1);
                gsh[row * GSTRIDE + col]           = acc[i][j][0];
                gsh[row * GSTRIDE + col + 1]       = acc[i][j][1];
                gsh[(row + 8) * GSTRIDE + col]     = acc[i][j][2];
                gsh[(row + 8) * GSTRIDE + col + 1] = acc[i][j][3];
            }
        __syncthreads();

        // ============ epilogue: bias + W_ih gather + LSTM + split ============
        if (tid < 128) {
            const int b = rowbase + tid;
            const int idx = g_idx[b];
            const float* wt = g_WihT + (size_t)idx * 2048;
            const float* gr = gsh + tid * GSTRIDE;
#pragma unroll
            for (int vl = 0; vl < 16; ++vl) {
                const int v = vt0 + vl;
                const int c0 = vl << 2;
                float gi = gr[c0 + 0] + sbias[c0 + 0] + wt[v];
                float gf = gr[c0 + 1] + sbias[c0 + 1] + wt[512 + v];
                float gg = gr[c0 + 2] + sbias[c0 + 2] + wt[1024 + v];
                float go = gr[c0 + 3] + sbias[c0 + 3] + wt[1536 + v];
                float si = 1.f / (1.f + expf(-gi));
                float sf = 1.f / (1.f + expf(-gf));
                float so = 1.f / (1.f + expf(-go));
                float tg = tanhf(gg);
                const size_t cix = ((size_t)b << 9) + v;
                float cn = sf * g_c[cix] + si * tg;
                g_c[cix] = cn;
                float h = so * tanhf(cn);
                g_h[cix] = h;
                split3(h, g_ha[nxt][0][cix], g_ha[nxt][1][cix], g_ha[nxt][2][cix]);
            }
        }
        grid_sync();

        // ============ phase B: softmax + argmax, one warp per batch row ======
        if (wid < 4) {
            int w = (bid << 2) + wid;
            const float* hr = g_h + ((size_t)w << 9);
            float4 hv[4];
#pragma unroll
            for (int q = 0; q < 4; ++q)
                hv[q] = *(const float4*)&hr[(q << 7) + (lane << 2)];

            float bm = -1e30f; int bi = 0x7fffffff;
#pragma unroll
            for (int q = 0; q < 4; ++q) {
                const float* f = (const float*)&hv[q];
#pragma unroll
                for (int cc = 0; cc < 4; ++cc) {
                    int vi = (q << 7) + (lane << 2) + cc;
                    float val = f[cc];
                    if (val > bm || (val == bm && vi < bi)) { bm = val; bi = vi; }
                }
            }
#pragma unroll
            for (int off = 16; off; off >>= 1) {
                float om = __shfl_down_sync(0xffffffffu, bm, off);
                int   oi = __shfl_down_sync(0xffffffffu, bi, off);
                if (om > bm || (om == bm && oi < bi)) { bm = om; bi = oi; }
            }
            bm = __shfl_sync(0xffffffffu, bm, 0);
            bi = __shfl_sync(0xffffffffu, bi, 0);

            float e[16];
            float s = 0.f;
#pragma unroll
            for (int q = 0; q < 4; ++q) {
                const float* f = (const float*)&hv[q];
#pragma unroll
                for (int cc = 0; cc < 4; ++cc) {
                    float ev = expf(f[cc] - bm);
                    e[(q << 2) + cc] = ev;
                    s += ev;
                }
            }
#pragma unroll
            for (int off = 16; off; off >>= 1)
                s += __shfl_xor_sync(0xffffffffu, s, off);
            float inv = 1.f / s;

            float* orow = out + ((size_t)w << 16) + ((size_t)t << 9);
#pragma unroll
            for (int q = 0; q < 4; ++q) {
                float4 ov;
                ov.x = e[(q << 2) + 0] * inv;
                ov.y = e[(q << 2) + 1] * inv;
                ov.z = e[(q << 2) + 2] * inv;
                ov.w = e[(q << 2) + 3] * inv;
                *(float4*)&orow[(q << 7) + (lane << 2)] = ov;
            }
            if (lane == 0) g_idx[w] = bi;
        }
        grid_sync();
    }
}

extern "C" void kernel_launch(void* const* d_in, const int* in_sizes, int n_in,
                              void* d_out, int out_size) {
    const float* x    = (const float*)d_in[0];
    const float* W_ih = (const float*)d_in[1];
    const float* W_hh = (const float*)d_in[2];
    const float* b_ih = (const float*)d_in[3];
    const float* b_hh = (const float*)d_in[4];
    float* out = (float*)d_out;
    cudaFuncSetAttribute(decoder_kernel,
                         cudaFuncAttributeMaxDynamicSharedMemorySize, SMEM_SZ);
    decoder_kernel<<<NBLK, NTHR, SMEM_SZ>>>(x, W_ih, W_hh, b_ih, b_hh, out);
}